// round 12
// baseline (speedup 1.0000x reference)
#include <cuda_runtime.h>

#define HWPIX 4096
#define NT 216
#define EMBROW 36928      // 64*577 floats per bucket
#define FROW 577
#define HALF_F 18464      // 32*577 floats
#define HALF_FB 73856     // bytes
#define NP 16             // pixel chunk (2 px per warp -> all warps live)
#define PSTRIDE 18
#define NSTG 3

typedef unsigned long long ull;

__device__ __forceinline__ ull pack_dup(float v) {
    ull r;
    asm("mov.b64 %0, {%1, %1};" : "=l"(r) : "f"(v));
    return r;
}
__device__ __forceinline__ void fma2(ull& acc, ull a, ull b) {
    asm("fma.rn.f32x2 %0, %1, %2, %0;" : "+l"(acc) : "l"(a), "l"(b));
}
__device__ __forceinline__ ull add2(ull a, ull b) {
    ull r;
    asm("add.rn.f32x2 %0, %1, %2;" : "=l"(r) : "l"(a), "l"(b));
    return r;
}
__device__ __forceinline__ void unpack2(float& lo, float& hi, ull v) {
    asm("mov.b64 {%0, %1}, %2;" : "=f"(lo), "=f"(hi) : "l"(v));
}
__device__ __forceinline__ unsigned smem_u32(const void* p) {
    unsigned a;
    asm("{ .reg .u64 t; cvta.to.shared.u64 t, %1; cvt.u32.u64 %0, t; }" : "=r"(a) : "l"(p));
    return a;
}

// ---------- device scratch ----------
__device__ __align__(16) float g_h[HWPIX * 64];   // conv1 out, HWC
__device__ __align__(16) float g_z[HWPIX * 64];   // dyn-conv out (relu'd), HWC
__device__ int g_hist16[16][NT];
__device__ int g_count[NT];
__device__ int g_start[NT];
__device__ int g_order[NT];
__device__ int g_pix[HWPIX];

// ---------- launch 1: conv1 (256 blocks, oc-split x4) + histogram (16 blocks) ----------
__global__ __launch_bounds__(256) void k_conv1hist(const float* __restrict__ x,
                                                   const float* __restrict__ w1,
                                                   const float* __restrict__ b1,
                                                   const int* __restrict__ buckets) {
    int blk = blockIdx.x;
    int tid = threadIdx.x;

    if (blk >= 256) {
        __shared__ int hist[NT];
        int hb = blk - 256;
        for (int i = tid; i < NT; i += 256) hist[i] = 0;
        __syncthreads();
        atomicAdd(&hist[buckets[hb * 256 + tid]], 1);
        __syncthreads();
        for (int i = tid; i < NT; i += 256) g_hist16[hb][i] = hist[i];
        return;
    }

    int tile = blk >> 2;
    int ocq = blk & 3;
    int g = tile >> 4;
    int y0 = ((tile >> 2) & 3) * 16, x0 = (tile & 3) * 16;

    __shared__ float xs[16][18][18];
    __shared__ __align__(16) float wsm[144 * 4];

    for (int idx = tid; idx < 576; idx += 256) {
        int i = idx / 144, m = idx - i * 144;
        wsm[m * 4 + i] = w1[(g * 16 + ocq * 4 + i) * 144 + m];
    }
    for (int idx = tid; idx < 16 * 324; idx += 256) {
        int ci = idx / 324, r = idx - ci * 324;
        int yl = r / 18, xl = r - yl * 18;
        int yy = y0 - 1 + yl, xx = x0 - 1 + xl;
        float v = 0.f;
        if ((unsigned)yy < 64u && (unsigned)xx < 64u)
            v = x[(g * 16 + ci) * HWPIX + yy * 64 + xx];
        xs[ci][yl][xl] = v;
    }
    __syncthreads();

    int ty = tid >> 4, tx = tid & 15;
    float acc[4];
#pragma unroll
    for (int i = 0; i < 4; i++) acc[i] = __ldg(&b1[g * 16 + ocq * 4 + i]);

    for (int ci = 0; ci < 16; ci++) {
#pragma unroll
        for (int s = 0; s < 9; s++) {
            float xv = xs[ci][ty + s / 3][tx + s % 3];
            float4 w = *(const float4*)&wsm[(ci * 9 + s) * 4];
            acc[0] += w.x * xv;
            acc[1] += w.y * xv;
            acc[2] += w.z * xv;
            acc[3] += w.w * xv;
        }
    }
    int gy = y0 + ty, gx = x0 + tx;
    float4 r;
    r.x = fmaxf(acc[0], 0.f);
    r.y = fmaxf(acc[1], 0.f);
    r.z = fmaxf(acc[2], 0.f);
    r.w = fmaxf(acc[3], 0.f);
    *(float4*)&g_h[(gy * 64 + gx) * 64 + g * 16 + ocq * 4] = r;
}

// ---------- launch 2: fused scan + scatter (16 blocks) ----------
__global__ __launch_bounds__(256) void k_scanscatter(const int* __restrict__ buckets) {
    __shared__ int cnt[256];
    __shared__ int scan[256];
    __shared__ int cur[NT];
    int tid = threadIdx.x;
    int j = blockIdx.x;

    int v = 0;
    if (tid < NT)
#pragma unroll
        for (int k = 0; k < 16; k++) v += g_hist16[k][tid];
    cnt[tid] = v;
    scan[tid] = v;
    __syncthreads();
    for (int off = 1; off < 256; off <<= 1) {
        int t = (tid >= off) ? scan[tid - off] : 0;
        __syncthreads();
        scan[tid] += t;
        __syncthreads();
    }
    if (tid < NT) {
        int excl = scan[tid] - v;
        int off = excl;
        for (int k = 0; k < j; k++) off += g_hist16[k][tid];
        cur[tid] = off;
        if (j == 0) {
            g_count[tid] = v;
            g_start[tid] = excl;
            int rank = 0;
            for (int q = 0; q < NT; q++) {
                int cq = cnt[q];
                rank += (cq > v) || (cq == v && q < tid);
            }
            g_order[rank] = tid;
        }
    }
    __syncthreads();
    int i = j * 256 + tid;
    int b = buckets[i];
    int pos = atomicAdd(&cur[b], 1);
    g_pix[pos] = i;
}

// ---------- launch 3: probe no-op (keeps k_dyn in ncu's captured slot) ----------
__global__ void k_probe() {}

// ---------- launch 4: dynamic conv, 432 blocks (bucket x o-half) ----------
__global__ __launch_bounds__(256) void k_dyn(const float* __restrict__ emb) {
    extern __shared__ float sm[];
    float* Fs = sm;                      // 32 x 577 (TMA target)
    float* patch = sm + HALF_F;          // 144 x 18
    __shared__ int pixels[NP];
    __shared__ __align__(8) ull mbar;

    int t = g_order[blockIdx.x >> 1];
    int half = blockIdx.x & 1;
    int tid = threadIdx.x;
    int n = g_count[t];
    int start = g_start[t];
    if (n == 0) return;

    unsigned mb = smem_u32(&mbar);
    if (tid == 0) {
        asm volatile("mbarrier.init.shared.b64 [%0], 1;" :: "r"(mb) : "memory");
        asm volatile("fence.proxy.async.shared::cta;" ::: "memory");
        asm volatile("mbarrier.arrive.expect_tx.shared.b64 _, [%0], %1;"
                     :: "r"(mb), "r"(HALF_FB) : "memory");
        asm volatile("cp.async.bulk.shared::cta.global.mbarrier::complete_tx::bytes "
                     "[%0], [%1], %2, [%3];"
                     :: "r"(smem_u32(Fs)),
                        "l"(emb + (size_t)t * EMBROW + half * HALF_F),
                        "r"(HALF_FB), "r"(mb) : "memory");
    }

    int o = tid & 31;        // lane: o within half (577 % 32 == 1 -> conflict-free)
    int w = tid >> 5;        // warp id: pixels {2w, 2w+1}

    // staging decomposition: 16px x 9 taps x 4 float4 = 576 units
    int pp[NSTG], soff[NSTG], sy[NSTG], sx[NSTG], chq[NSTG];
    bool qv_ok[NSTG];
#pragma unroll
    for (int i = 0; i < NSTG; i++) {
        int q = tid + i * 256;
        qv_ok[i] = (q < 576);
        int qq = qv_ok[i] ? q : 0;
        int p = qq / 36;
        int r = qq - p * 36;
        int cq = r & 3, s = r >> 2;
        pp[i] = p;
        sy[i] = s / 3 - 1;
        sx[i] = s % 3 - 1;
        soff[i] = ((cq * 4) * 9 + s) * PSTRIDE + p;
        chq[i] = cq * 4;
    }

    float4 sv[NSTG];
    bool waited = false;

    for (int pb = 0; pb < n; pb += NP) {
        int npc = min(NP, n - pb);
        bool live = (w * 2 < npc);
        __syncthreads();
        if (tid < NP) pixels[tid] = g_pix[start + pb + min(tid, npc - 1)];
        __syncthreads();

        // stage slab c=0
#pragma unroll
        for (int i = 0; i < NSTG; i++) {
            if (qv_ok[i]) {
                int pix = pixels[pp[i]];
                int yy = (pix >> 6) + sy[i], xx = (pix & 63) + sx[i];
                float4 v = make_float4(0.f, 0.f, 0.f, 0.f);
                if ((unsigned)yy < 64u && (unsigned)xx < 64u)
                    v = *(const float4*)&g_h[((yy << 6) + xx) * 64 + chq[i]];
                sv[i] = v;
            }
        }

        ull accA = 0, accB = 0;   // even/odd ck chains, px pair {2w, 2w+1}

        for (int c = 0; c < 4; c++) {
#pragma unroll
            for (int i = 0; i < NSTG; i++) {
                if (qv_ok[i]) {
                    patch[soff[i] + 0 * 9 * PSTRIDE] = sv[i].x;
                    patch[soff[i] + 1 * 9 * PSTRIDE] = sv[i].y;
                    patch[soff[i] + 2 * 9 * PSTRIDE] = sv[i].z;
                    patch[soff[i] + 3 * 9 * PSTRIDE] = sv[i].w;
                }
            }
            __syncthreads();

            if (c < 3) {
                int c0n = (c + 1) * 16;
#pragma unroll
                for (int i = 0; i < NSTG; i++) {
                    if (qv_ok[i]) {
                        int pix = pixels[pp[i]];
                        int yy = (pix >> 6) + sy[i], xx = (pix & 63) + sx[i];
                        float4 v = make_float4(0.f, 0.f, 0.f, 0.f);
                        if ((unsigned)yy < 64u && (unsigned)xx < 64u)
                            v = *(const float4*)&g_h[((yy << 6) + xx) * 64 + c0n + chq[i]];
                        sv[i] = v;
                    }
                }
            }

            if (!waited) {
                unsigned done;
                do {
                    asm volatile("{\n\t.reg .pred p;\n\t"
                                 "mbarrier.try_wait.parity.acquire.cta.shared::cta.b64 p, [%1], 0, 0x989680;\n\t"
                                 "selp.b32 %0, 1, 0, p;\n\t}"
                                 : "=r"(done) : "r"(mb) : "memory");
                } while (!done);
                waited = true;
            }

            if (live) {
                const float* Fo = Fs + o * FROW + c * 144;
                const float* Pb = patch + w * 2;
#pragma unroll 8
                for (int ck = 0; ck < 144; ck += 2) {
                    ull d0 = pack_dup(Fo[ck]);
                    fma2(accA, d0, *(const ull*)&Pb[ck * PSTRIDE]);
                    ull d1 = pack_dup(Fo[ck + 1]);
                    fma2(accB, d1, *(const ull*)&Pb[(ck + 1) * PSTRIDE]);
                }
            }
            __syncthreads();
        }

        if (live) {
            float a0, a1;
            unpack2(a0, a1, add2(accA, accB));
            float bs = Fs[o * FROW + 576];
            int p0 = w * 2;
            {
                int pix = pixels[p0];
                g_z[pix * 64 + half * 32 + o] = fmaxf(a0 + bs, 0.f);
            }
            if (p0 + 1 < npc) {
                int pix = pixels[p0 + 1];
                g_z[pix * 64 + half * 32 + o] = fmaxf(a1 + bs, 0.f);
            }
        }
    }
}

// ---------- launch 5: 1x1 conv + b2 + residual + relu (256 blocks x 16 px) ----------
__global__ __launch_bounds__(256) void k_body2(const float* __restrict__ x,
                                               const float* __restrict__ w2,
                                               const float* __restrict__ b2,
                                               float* __restrict__ out) {
    __shared__ __align__(16) float zs[16][68];    // [p][c], row pad 68
    __shared__ __align__(16) float w2s[4096];     // [o][c] linear
    int tid = threadIdx.x;
    int pixbase = blockIdx.x * 16;

#pragma unroll
    for (int k = 0; k < 4; k++) {
        int idx = (tid + k * 256) * 4;
        *(float4*)&w2s[idx] = *(const float4*)(w2 + idx);
    }
    {
        int p = tid >> 4, c4 = (tid & 15) * 4;
        *(float4*)&zs[p][c4] = *(const float4*)&g_z[(pixbase + p) * 64 + c4];
    }

    int px = tid & 15;
    int og = tid >> 4;

    float resid[4];
#pragma unroll
    for (int i = 0; i < 4; i++) resid[i] = x[(og * 4 + i) * HWPIX + pixbase + px];

    float acc[4];
#pragma unroll
    for (int i = 0; i < 4; i++) acc[i] = __ldg(&b2[og * 4 + i]);

    __syncthreads();

#pragma unroll
    for (int c4 = 0; c4 < 64; c4 += 4) {
        float4 z = *(const float4*)&zs[px][c4];
#pragma unroll
        for (int i = 0; i < 4; i++) {
            float4 w = *(const float4*)&w2s[(og * 4 + i) * 64 + c4];
            acc[i] += w.x * z.x;
            acc[i] += w.y * z.y;
            acc[i] += w.z * z.z;
            acc[i] += w.w * z.w;
        }
    }

#pragma unroll
    for (int i = 0; i < 4; i++) {
        int o = og * 4 + i;
        out[o * HWPIX + pixbase + px] = fmaxf(acc[i] + resid[i], 0.f);
    }
}

extern "C" void kernel_launch(void* const* d_in, const int* in_sizes, int n_in,
                              void* d_out, int out_size) {
    const float* x   = (const float*)d_in[0];
    const int* bk    = (const int*)d_in[1];
    const float* w1  = (const float*)d_in[2];
    const float* b1  = (const float*)d_in[3];
    const float* emb = (const float*)d_in[4];
    const float* w2  = (const float*)d_in[5];
    const float* b2  = (const float*)d_in[6];
    float* out = (float*)d_out;

    k_conv1hist<<<272, 256>>>(x, w1, b1, bk);
    k_scanscatter<<<16, 256>>>(bk);
    k_probe<<<1, 32>>>();   // keeps k_dyn in ncu's captured slot

    size_t smem = (size_t)(HALF_F + 144 * PSTRIDE) * sizeof(float); // 84224 B
    cudaFuncSetAttribute(k_dyn, cudaFuncAttributeMaxDynamicSharedMemorySize, (int)smem);
    k_dyn<<<NT * 2, 256, smem>>>(emb);

    k_body2<<<256, 256>>>(x, w2, b2, out);
}

// round 13
// speedup vs baseline: 1.1475x; 1.1475x over previous
#include <cuda_runtime.h>

#define HWPIX 4096
#define NT 216
#define EMBROW 36928      // 64*577 floats per bucket
#define FROW 577
#define HALF_F 18464      // 32*577 floats
#define HALF_FB 73856     // bytes
#define NP 16             // pixel chunk
#define PROW 576          // patch row length (floats) per pixel

typedef unsigned long long ull;

__device__ __forceinline__ unsigned smem_u32(const void* p) {
    unsigned a;
    asm("{ .reg .u64 t; cvta.to.shared.u64 t, %1; cvt.u32.u64 %0, t; }" : "=r"(a) : "l"(p));
    return a;
}

// ---------- device scratch ----------
__device__ __align__(16) float g_h[HWPIX * 64];   // conv1 out, HWC
__device__ __align__(16) float g_z[HWPIX * 64];   // dyn-conv out (relu'd), HWC
__device__ int g_hist16[16][NT];
__device__ int g_count[NT];
__device__ int g_start[NT];
__device__ int g_order[NT];
__device__ int g_pix[HWPIX];

// ---------- launch 1: conv1 (256 blocks, oc-split x4) + histogram (16 blocks) ----------
__global__ __launch_bounds__(256) void k_conv1hist(const float* __restrict__ x,
                                                   const float* __restrict__ w1,
                                                   const float* __restrict__ b1,
                                                   const int* __restrict__ buckets) {
    int blk = blockIdx.x;
    int tid = threadIdx.x;

    if (blk >= 256) {
        __shared__ int hist[NT];
        int hb = blk - 256;
        for (int i = tid; i < NT; i += 256) hist[i] = 0;
        __syncthreads();
        atomicAdd(&hist[buckets[hb * 256 + tid]], 1);
        __syncthreads();
        for (int i = tid; i < NT; i += 256) g_hist16[hb][i] = hist[i];
        return;
    }

    int tile = blk >> 2;
    int ocq = blk & 3;
    int g = tile >> 4;
    int y0 = ((tile >> 2) & 3) * 16, x0 = (tile & 3) * 16;

    __shared__ float xs[16][18][18];
    __shared__ __align__(16) float wsm[144 * 4];

    for (int idx = tid; idx < 576; idx += 256) {
        int i = idx / 144, m = idx - i * 144;
        wsm[m * 4 + i] = w1[(g * 16 + ocq * 4 + i) * 144 + m];
    }
    for (int idx = tid; idx < 16 * 324; idx += 256) {
        int ci = idx / 324, r = idx - ci * 324;
        int yl = r / 18, xl = r - yl * 18;
        int yy = y0 - 1 + yl, xx = x0 - 1 + xl;
        float v = 0.f;
        if ((unsigned)yy < 64u && (unsigned)xx < 64u)
            v = x[(g * 16 + ci) * HWPIX + yy * 64 + xx];
        xs[ci][yl][xl] = v;
    }
    __syncthreads();

    int ty = tid >> 4, tx = tid & 15;
    float acc[4];
#pragma unroll
    for (int i = 0; i < 4; i++) acc[i] = __ldg(&b1[g * 16 + ocq * 4 + i]);

    for (int ci = 0; ci < 16; ci++) {
#pragma unroll
        for (int s = 0; s < 9; s++) {
            float xv = xs[ci][ty + s / 3][tx + s % 3];
            float4 w = *(const float4*)&wsm[(ci * 9 + s) * 4];
            acc[0] += w.x * xv;
            acc[1] += w.y * xv;
            acc[2] += w.z * xv;
            acc[3] += w.w * xv;
        }
    }
    int gy = y0 + ty, gx = x0 + tx;
    float4 r;
    r.x = fmaxf(acc[0], 0.f);
    r.y = fmaxf(acc[1], 0.f);
    r.z = fmaxf(acc[2], 0.f);
    r.w = fmaxf(acc[3], 0.f);
    *(float4*)&g_h[(gy * 64 + gx) * 64 + g * 16 + ocq * 4] = r;
}

// ---------- launch 2: fused scan + scatter (16 blocks) ----------
__global__ __launch_bounds__(256) void k_scanscatter(const int* __restrict__ buckets) {
    __shared__ int cnt[256];
    __shared__ int scan[256];
    __shared__ int cur[NT];
    int tid = threadIdx.x;
    int j = blockIdx.x;

    int v = 0;
    if (tid < NT)
#pragma unroll
        for (int k = 0; k < 16; k++) v += g_hist16[k][tid];
    cnt[tid] = v;
    scan[tid] = v;
    __syncthreads();
    for (int off = 1; off < 256; off <<= 1) {
        int t = (tid >= off) ? scan[tid - off] : 0;
        __syncthreads();
        scan[tid] += t;
        __syncthreads();
    }
    if (tid < NT) {
        int excl = scan[tid] - v;
        int off = excl;
        for (int k = 0; k < j; k++) off += g_hist16[k][tid];
        cur[tid] = off;
        if (j == 0) {
            g_count[tid] = v;
            g_start[tid] = excl;
            int rank = 0;
            for (int q = 0; q < NT; q++) {
                int cq = cnt[q];
                rank += (cq > v) || (cq == v && q < tid);
            }
            g_order[rank] = tid;
        }
    }
    __syncthreads();
    int i = j * 256 + tid;
    int b = buckets[i];
    int pos = atomicAdd(&cur[b], 1);
    g_pix[pos] = i;
}

// ---------- launch 3: probe no-op (keeps k_dyn in ncu's captured slot) ----------
__global__ void k_probe() {}

// ---------- launch 4: dynamic conv, 432 blocks (bucket x o-half), K-split GEMM ----------
__global__ __launch_bounds__(256) void k_dyn(const float* __restrict__ emb) {
    extern __shared__ float sm[];
    float* Fs = sm;                      // 32 x 577 (TMA target), 73856 B
    float* patch = sm + HALF_F;          // 16 px x 576 ck row-major, 36864 B (aliased as red)
    __shared__ int pixels[NP];
    __shared__ __align__(8) ull mbar;

    int t = g_order[blockIdx.x >> 1];
    int half = blockIdx.x & 1;
    int tid = threadIdx.x;
    int n = g_count[t];
    int start = g_start[t];
    if (n == 0) return;

    unsigned mb = smem_u32(&mbar);
    if (tid == 0) {
        asm volatile("mbarrier.init.shared.b64 [%0], 1;" :: "r"(mb) : "memory");
        asm volatile("fence.proxy.async.shared::cta;" ::: "memory");
        asm volatile("mbarrier.arrive.expect_tx.shared.b64 _, [%0], %1;"
                     :: "r"(mb), "r"(HALF_FB) : "memory");
        asm volatile("cp.async.bulk.shared::cta.global.mbarrier::complete_tx::bytes "
                     "[%0], [%1], %2, [%3];"
                     :: "r"(smem_u32(Fs)),
                        "l"(emb + (size_t)t * EMBROW + half * HALF_F),
                        "r"(HALF_FB), "r"(mb) : "memory");
    }

    int o = tid & 31;        // lane -> output channel within half
    int w = tid >> 5;        // warp -> ck range [w*72, w*72+72)

    // staging decomposition: 2304 units = 16 px x 16 c4 x 9 s; exactly 9 per thread
    int pp[9], sy[9], sx[9], stso[9], ldo[9];
#pragma unroll
    for (int i = 0; i < 9; i++) {
        int u = tid + i * 256;
        int p = u / 144;
        int m = u - p * 144;
        int c4 = m / 9;
        int s = m - c4 * 9;
        pp[i] = p;
        sy[i] = s / 3 - 1;
        sx[i] = s % 3 - 1;
        stso[i] = p * PROW + c4 * 36 + s;   // + 9*q for q-th channel of the float4
        ldo[i] = c4 * 4;
    }

    bool waited = false;

    for (int pb = 0; pb < n; pb += NP) {
        int npc = min(NP, n - pb);
        __syncthreads();                      // patch/red free from previous chunk
        if (tid < NP) pixels[tid] = g_pix[start + pb + min(tid, npc - 1)];
        __syncthreads();

        // stage ALL 576 ck for 16 px into [px][ck] rows
#pragma unroll
        for (int i = 0; i < 9; i++) {
            int pix = pixels[pp[i]];
            int yy = (pix >> 6) + sy[i], xx = (pix & 63) + sx[i];
            float4 v = make_float4(0.f, 0.f, 0.f, 0.f);
            if ((unsigned)yy < 64u && (unsigned)xx < 64u)
                v = *(const float4*)&g_h[((yy << 6) + xx) * 64 + ldo[i]];
            patch[stso[i]]      = v.x;
            patch[stso[i] + 9]  = v.y;
            patch[stso[i] + 18] = v.z;
            patch[stso[i] + 27] = v.w;
        }
        __syncthreads();

        if (!waited) {
            unsigned done;
            do {
                asm volatile("{\n\t.reg .pred p;\n\t"
                             "mbarrier.try_wait.parity.acquire.cta.shared::cta.b64 p, [%1], 0, 0x989680;\n\t"
                             "selp.b32 %0, 1, 0, p;\n\t}"
                             : "=r"(done) : "r"(mb) : "memory");
            } while (!done);
            waited = true;
        }

        // K-split GEMM: warp w covers ck in [w*72, w*72+72); lane = o; acc over 16 px
        float acc[NP];
#pragma unroll
        for (int p = 0; p < NP; p++) acc[p] = 0.f;

        const float* Fo = Fs + o * FROW + w * 72;
#pragma unroll 2
        for (int g = 0; g < 18; g++) {
            int ck = g * 4;
            float fA = Fo[ck];
            float fB = Fo[ck + 1];
            float fC = Fo[ck + 2];
            float fD = Fo[ck + 3];
            const float* Pb = patch + w * 72 + ck;
#pragma unroll
            for (int p = 0; p < NP; p++) {
                float4 pv = *(const float4*)&Pb[p * PROW];   // broadcast LDS.128
                acc[p] += fA * pv.x;
                acc[p] += fB * pv.y;
                acc[p] += fC * pv.z;
                acc[p] += fD * pv.w;
            }
        }
        __syncthreads();     // patch reads done; reuse as reduction buffer

        float* red = patch;
#pragma unroll
        for (int p = 0; p < NP; p++)
            red[(w * NP + p) * 32 + o] = acc[p];
        __syncthreads();

        // reduce 8 partials -> bias + relu -> g_z ; thread handles (o, p) and (o, p+8)
#pragma unroll
        for (int r = 0; r < 2; r++) {
            int p = (tid >> 5) + r * 8;
            if (p < npc) {
                float s = 0.f;
#pragma unroll
                for (int ww = 0; ww < 8; ww++)
                    s += red[(ww * NP + p) * 32 + o];
                s += Fs[o * FROW + 576];
                int pix = pixels[p];
                g_z[pix * 64 + half * 32 + o] = fmaxf(s, 0.f);
            }
        }
    }
}

// ---------- launch 5: 1x1 conv + b2 + residual + relu (256 blocks x 16 px) ----------
__global__ __launch_bounds__(256) void k_body2(const float* __restrict__ x,
                                               const float* __restrict__ w2,
                                               const float* __restrict__ b2,
                                               float* __restrict__ out) {
    __shared__ __align__(16) float zs[16][68];    // [p][c], row pad 68
    __shared__ __align__(16) float w2s[4096];     // [o][c] linear
    int tid = threadIdx.x;
    int pixbase = blockIdx.x * 16;

#pragma unroll
    for (int k = 0; k < 4; k++) {
        int idx = (tid + k * 256) * 4;
        *(float4*)&w2s[idx] = *(const float4*)(w2 + idx);
    }
    {
        int p = tid >> 4, c4 = (tid & 15) * 4;
        *(float4*)&zs[p][c4] = *(const float4*)&g_z[(pixbase + p) * 64 + c4];
    }

    int px = tid & 15;
    int og = tid >> 4;

    float resid[4];
#pragma unroll
    for (int i = 0; i < 4; i++) resid[i] = x[(og * 4 + i) * HWPIX + pixbase + px];

    float acc[4];
#pragma unroll
    for (int i = 0; i < 4; i++) acc[i] = __ldg(&b2[og * 4 + i]);

    __syncthreads();

#pragma unroll
    for (int c4 = 0; c4 < 64; c4 += 4) {
        float4 z = *(const float4*)&zs[px][c4];
#pragma unroll
        for (int i = 0; i < 4; i++) {
            float4 w = *(const float4*)&w2s[(og * 4 + i) * 64 + c4];
            acc[i] += w.x * z.x;
            acc[i] += w.y * z.y;
            acc[i] += w.z * z.z;
            acc[i] += w.w * z.w;
        }
    }

#pragma unroll
    for (int i = 0; i < 4; i++) {
        int o = og * 4 + i;
        out[o * HWPIX + pixbase + px] = fmaxf(acc[i] + resid[i], 0.f);
    }
}

extern "C" void kernel_launch(void* const* d_in, const int* in_sizes, int n_in,
                              void* d_out, int out_size) {
    const float* x   = (const float*)d_in[0];
    const int* bk    = (const int*)d_in[1];
    const float* w1  = (const float*)d_in[2];
    const float* b1  = (const float*)d_in[3];
    const float* emb = (const float*)d_in[4];
    const float* w2  = (const float*)d_in[5];
    const float* b2  = (const float*)d_in[6];
    float* out = (float*)d_out;

    k_conv1hist<<<272, 256>>>(x, w1, b1, bk);
    k_scanscatter<<<16, 256>>>(bk);
    k_probe<<<1, 32>>>();   // keeps k_dyn in ncu's captured slot

    size_t smem = (size_t)(HALF_F + NP * PROW) * sizeof(float); // 110720 B -> 2 blocks/SM
    cudaFuncSetAttribute(k_dyn, cudaFuncAttributeMaxDynamicSharedMemorySize, (int)smem);
    k_dyn<<<NT * 2, 256, smem>>>(emb);

    k_body2<<<256, 256>>>(x, w2, b2, out);
}

// round 15
// speedup vs baseline: 1.3497x; 1.1762x over previous
#include <cuda_runtime.h>

#define HWPIX 4096
#define NT 216
#define EMBROW 36928      // 64*577 floats per bucket
#define FROW 577
#define HALF_F 18464      // 32*577 floats
#define HALF_FB 73856     // bytes
#define NP 16             // pixel chunk
#define PROW 576          // patch row length (floats) per pixel

typedef unsigned long long ull;

__device__ __forceinline__ unsigned smem_u32(const void* p) {
    unsigned a;
    asm("{ .reg .u64 t; cvta.to.shared.u64 t, %1; cvt.u32.u64 %0, t; }" : "=r"(a) : "l"(p));
    return a;
}

// ---------- device scratch ----------
__device__ __align__(16) float g_h[HWPIX * 64];   // conv1 out, HWC
__device__ __align__(16) float g_z[HWPIX * 64];   // dyn-conv out (relu'd), HWC
__device__ int g_hist16[16][NT];
__device__ int g_count[NT];
__device__ int g_start[NT];
__device__ int g_order[NT];
__device__ int g_pix[HWPIX];

// ---------- launch 1: conv1 (256 blocks, oc-split x4) + histogram (16 blocks) ----------
__global__ __launch_bounds__(256) void k_conv1hist(const float* __restrict__ x,
                                                   const float* __restrict__ w1,
                                                   const float* __restrict__ b1,
                                                   const int* __restrict__ buckets) {
    int blk = blockIdx.x;
    int tid = threadIdx.x;

    if (blk >= 256) {
        __shared__ int hist[NT];
        int hb = blk - 256;
        for (int i = tid; i < NT; i += 256) hist[i] = 0;
        __syncthreads();
        atomicAdd(&hist[buckets[hb * 256 + tid]], 1);
        __syncthreads();
        for (int i = tid; i < NT; i += 256) g_hist16[hb][i] = hist[i];
        return;
    }

    int tile = blk >> 2;
    int ocq = blk & 3;
    int g = tile >> 4;
    int y0 = ((tile >> 2) & 3) * 16, x0 = (tile & 3) * 16;

    __shared__ float xs[16][18][18];
    __shared__ __align__(16) float wsm[144 * 4];

    for (int idx = tid; idx < 576; idx += 256) {
        int i = idx / 144, m = idx - i * 144;
        wsm[m * 4 + i] = w1[(g * 16 + ocq * 4 + i) * 144 + m];
    }
    for (int idx = tid; idx < 16 * 324; idx += 256) {
        int ci = idx / 324, r = idx - ci * 324;
        int yl = r / 18, xl = r - yl * 18;
        int yy = y0 - 1 + yl, xx = x0 - 1 + xl;
        float v = 0.f;
        if ((unsigned)yy < 64u && (unsigned)xx < 64u)
            v = x[(g * 16 + ci) * HWPIX + yy * 64 + xx];
        xs[ci][yl][xl] = v;
    }
    __syncthreads();

    int ty = tid >> 4, tx = tid & 15;
    float acc[4];
#pragma unroll
    for (int i = 0; i < 4; i++) acc[i] = __ldg(&b1[g * 16 + ocq * 4 + i]);

    for (int ci = 0; ci < 16; ci++) {
#pragma unroll
        for (int s = 0; s < 9; s++) {
            float xv = xs[ci][ty + s / 3][tx + s % 3];
            float4 w = *(const float4*)&wsm[(ci * 9 + s) * 4];
            acc[0] += w.x * xv;
            acc[1] += w.y * xv;
            acc[2] += w.z * xv;
            acc[3] += w.w * xv;
        }
    }
    int gy = y0 + ty, gx = x0 + tx;
    float4 r;
    r.x = fmaxf(acc[0], 0.f);
    r.y = fmaxf(acc[1], 0.f);
    r.z = fmaxf(acc[2], 0.f);
    r.w = fmaxf(acc[3], 0.f);
    *(float4*)&g_h[(gy * 64 + gx) * 64 + g * 16 + ocq * 4] = r;
}

// ---------- launch 2: fused scan + scatter (16 blocks) ----------
__global__ __launch_bounds__(256) void k_scanscatter(const int* __restrict__ buckets) {
    __shared__ int cnt[256];
    __shared__ int scan[256];
    __shared__ int cur[NT];
    int tid = threadIdx.x;
    int j = blockIdx.x;

    int v = 0;
    if (tid < NT)
#pragma unroll
        for (int k = 0; k < 16; k++) v += g_hist16[k][tid];
    cnt[tid] = v;
    scan[tid] = v;
    __syncthreads();
    for (int off = 1; off < 256; off <<= 1) {
        int t = (tid >= off) ? scan[tid - off] : 0;
        __syncthreads();
        scan[tid] += t;
        __syncthreads();
    }
    if (tid < NT) {
        int excl = scan[tid] - v;
        int off = excl;
        for (int k = 0; k < j; k++) off += g_hist16[k][tid];
        cur[tid] = off;
        if (j == 0) {
            g_count[tid] = v;
            g_start[tid] = excl;
            int rank = 0;
            for (int q = 0; q < NT; q++) {
                int cq = cnt[q];
                rank += (cq > v) || (cq == v && q < tid);
            }
            g_order[rank] = tid;
        }
    }
    __syncthreads();
    int i = j * 256 + tid;
    int b = buckets[i];
    int pos = atomicAdd(&cur[b], 1);
    g_pix[pos] = i;
}

// ---------- K-split GEMM variant (NPX pixels), uniform per block ----------
template<int NPX>
__device__ __forceinline__ void gemm_ksplit(const float* __restrict__ Fs,
                                            float* __restrict__ patch,
                                            int o, int w) {
    float acc[NPX];
#pragma unroll
    for (int p = 0; p < NPX; p++) acc[p] = 0.f;

    const float* Fo = Fs + o * FROW + w * 72;
    const float* Pb = patch + w * 72;
#pragma unroll 2
    for (int g = 0; g < 18; g++) {
        int ck = g * 4;
        float fA = Fo[ck];
        float fB = Fo[ck + 1];
        float fC = Fo[ck + 2];
        float fD = Fo[ck + 3];
#pragma unroll
        for (int p = 0; p < NPX; p++) {
            float4 pv = *(const float4*)&Pb[p * PROW + ck];   // broadcast LDS.128
            acc[p] += fA * pv.x;
            acc[p] += fB * pv.y;
            acc[p] += fC * pv.z;
            acc[p] += fD * pv.w;
        }
    }
    __syncthreads();   // uniform branch: all threads here; patch reads done
    float* red = patch;
#pragma unroll
    for (int p = 0; p < NPX; p++)
        red[(w * NP + p) * 32 + o] = acc[p];
}

// ---------- launch 3: dynamic conv, 432 blocks (bucket x o-half), K-split GEMM ----------
__global__ __launch_bounds__(256) void k_dyn(const float* __restrict__ emb) {
    extern __shared__ float sm[];
    float* Fs = sm;                      // 32 x 577 (TMA target), 73856 B
    float* patch = sm + HALF_F;          // 16 px x 576 ck row-major (aliased as red)
    __shared__ int pixels[NP];
    __shared__ __align__(8) ull mbar;

    int t = g_order[blockIdx.x >> 1];
    int half = blockIdx.x & 1;
    int tid = threadIdx.x;
    int n = g_count[t];
    int start = g_start[t];
    if (n == 0) return;

    unsigned mb = smem_u32(&mbar);
    if (tid == 0) {
        asm volatile("mbarrier.init.shared.b64 [%0], 1;" :: "r"(mb) : "memory");
        asm volatile("fence.proxy.async.shared::cta;" ::: "memory");
        asm volatile("mbarrier.arrive.expect_tx.shared.b64 _, [%0], %1;"
                     :: "r"(mb), "r"(HALF_FB) : "memory");
        asm volatile("cp.async.bulk.shared::cta.global.mbarrier::complete_tx::bytes "
                     "[%0], [%1], %2, [%3];"
                     :: "r"(smem_u32(Fs)),
                        "l"(emb + (size_t)t * EMBROW + half * HALF_F),
                        "r"(HALF_FB), "r"(mb) : "memory");
    }

    int o = tid & 31;        // lane -> output channel within half
    int w = tid >> 5;        // warp -> ck range [w*72, w*72+72)

    // staging decomposition: 2304 units = 16 px x 16 c4 x 9 s; exactly 9 per thread
    int pp[9], sy[9], sx[9], stso[9], ldo[9];
#pragma unroll
    for (int i = 0; i < 9; i++) {
        int u = tid + i * 256;
        int p = u / 144;
        int m = u - p * 144;
        int c4 = m / 9;
        int s = m - c4 * 9;
        pp[i] = p;
        sy[i] = s / 3 - 1;
        sx[i] = s % 3 - 1;
        stso[i] = p * PROW + c4 * 36 + s;
        ldo[i] = c4 * 4;
    }

    bool waited = false;

    for (int pb = 0; pb < n; pb += NP) {
        int npc = min(NP, n - pb);
        int npc4 = min(NP, (npc + 3) & ~3);
        __syncthreads();                      // patch/red free from previous chunk
        if (tid < NP) pixels[tid] = g_pix[start + pb + min(tid, npc - 1)];
        __syncthreads();

        // stage rows < npc4 (clamped duplicates -> all staged rows valid)
#pragma unroll
        for (int i = 0; i < 9; i++) {
            if (pp[i] < npc4) {
                int pix = pixels[pp[i]];
                int yy = (pix >> 6) + sy[i], xx = (pix & 63) + sx[i];
                float4 v = make_float4(0.f, 0.f, 0.f, 0.f);
                if ((unsigned)yy < 64u && (unsigned)xx < 64u)
                    v = *(const float4*)&g_h[((yy << 6) + xx) * 64 + ldo[i]];
                patch[stso[i]]      = v.x;
                patch[stso[i] + 9]  = v.y;
                patch[stso[i] + 18] = v.z;
                patch[stso[i] + 27] = v.w;
            }
        }
        __syncthreads();

        if (!waited) {
            unsigned done;
            do {
                asm volatile("{\n\t.reg .pred p;\n\t"
                             "mbarrier.try_wait.parity.acquire.cta.shared::cta.b64 p, [%1], 0, 0x989680;\n\t"
                             "selp.b32 %0, 1, 0, p;\n\t}"
                             : "=r"(done) : "r"(mb) : "memory");
            } while (!done);
            waited = true;
        }

        // K-split GEMM sized to this chunk (npc4 uniform -> uniform switch)
        switch (npc4) {
            case 16: gemm_ksplit<16>(Fs, patch, o, w); break;
            case 12: gemm_ksplit<12>(Fs, patch, o, w); break;
            case 8:  gemm_ksplit<8>(Fs, patch, o, w); break;
            default: gemm_ksplit<4>(Fs, patch, o, w); break;
        }
        __syncthreads();

        // reduce 8 partials -> bias + relu -> g_z
        float* red = patch;
#pragma unroll
        for (int r = 0; r < 2; r++) {
            int p = (tid >> 5) + r * 8;
            if (p < npc) {
                float s = 0.f;
#pragma unroll
                for (int ww = 0; ww < 8; ww++)
                    s += red[(ww * NP + p) * 32 + o];
                s += Fs[o * FROW + 576];
                int pix = pixels[p];
                g_z[pix * 64 + half * 32 + o] = fmaxf(s, 0.f);
            }
        }
    }
}

// ---------- launch 4: 1x1 conv + b2 + residual + relu (256 blocks x 16 px) ----------
__global__ __launch_bounds__(256) void k_body2(const float* __restrict__ x,
                                               const float* __restrict__ w2,
                                               const float* __restrict__ b2,
                                               float* __restrict__ out) {
    __shared__ __align__(16) float zs[16][68];    // [p][c], row pad 68
    __shared__ __align__(16) float w2s[4096];     // [o][c] linear
    int tid = threadIdx.x;
    int pixbase = blockIdx.x * 16;

#pragma unroll
    for (int k = 0; k < 4; k++) {
        int idx = (tid + k * 256) * 4;
        *(float4*)&w2s[idx] = *(const float4*)(w2 + idx);
    }
    {
        int p = tid >> 4, c4 = (tid & 15) * 4;
        *(float4*)&zs[p][c4] = *(const float4*)&g_z[(pixbase + p) * 64 + c4];
    }

    int px = tid & 15;
    int og = tid >> 4;

    float resid[4];
#pragma unroll
    for (int i = 0; i < 4; i++) resid[i] = x[(og * 4 + i) * HWPIX + pixbase + px];

    float acc[4];
#pragma unroll
    for (int i = 0; i < 4; i++) acc[i] = __ldg(&b2[og * 4 + i]);

    __syncthreads();

#pragma unroll
    for (int c4 = 0; c4 < 64; c4 += 4) {
        float4 z = *(const float4*)&zs[px][c4];
#pragma unroll
        for (int i = 0; i < 4; i++) {
            float4 w = *(const float4*)&w2s[(og * 4 + i) * 64 + c4];
            acc[i] += w.x * z.x;
            acc[i] += w.y * z.y;
            acc[i] += w.z * z.z;
            acc[i] += w.w * z.w;
        }
    }

#pragma unroll
    for (int i = 0; i < 4; i++) {
        int o = og * 4 + i;
        out[o * HWPIX + pixbase + px] = fmaxf(acc[i] + resid[i], 0.f);
    }
}

extern "C" void kernel_launch(void* const* d_in, const int* in_sizes, int n_in,
                              void* d_out, int out_size) {
    const float* x   = (const float*)d_in[0];
    const int* bk    = (const int*)d_in[1];
    const float* w1  = (const float*)d_in[2];
    const float* b1  = (const float*)d_in[3];
    const float* emb = (const float*)d_in[4];
    const float* w2  = (const float*)d_in[5];
    const float* b2  = (const float*)d_in[6];
    float* out = (float*)d_out;

    k_conv1hist<<<272, 256>>>(x, w1, b1, bk);
    k_scanscatter<<<16, 256>>>(bk);

    size_t smem = (size_t)(HALF_F + NP * PROW) * sizeof(float); // 110720 B -> 2 blocks/SM
    cudaFuncSetAttribute(k_dyn, cudaFuncAttributeMaxDynamicSharedMemorySize, (int)smem);
    k_dyn<<<NT * 2, 256, smem>>>(emb);

    k_body2<<<256, 256>>>(x, w2, b2, out);
}